// round 1
// baseline (speedup 1.0000x reference)
#include <cuda_runtime.h>
#include <cuda_bf16.h>

// VACF: out[t] = mean(flat[t:] * flat[:-t]), flat = vel.reshape(T, D)
// T = 10000, D = 3000, W = 100 (= out_size)
//
// S[t] = sum_i sum_j x[i][j] * x[i+t][j]  (zero-padded beyond T)
// out[t] = S[t] / ((T - t) * D)

#define T_DIM 10000
#define D_DIM 3000
#define LPW   13          // lags per warp
#define NWARP 8           // 8 * 13 = 104 >= 100 lags covered
#define TT    208         // time rows computed per block (multiple of 13)
#define HALO  104         // max lag (103) + 1 slide slot
#define SH_ROWS (TT + HALO)   // 312
#define CB    64          // columns per block (f32x2: 2 per lane)
#define NTHREADS 256

__device__ double g_sum[128];

__device__ __forceinline__ unsigned long long ffma2(
    unsigned long long a, unsigned long long b, unsigned long long c) {
    unsigned long long d;
    asm("fma.rn.f32x2 %0, %1, %2, %3;" : "=l"(d) : "l"(a), "l"(b), "l"(c));
    return d;
}

__global__ void vacf_zero_kernel() {
    g_sum[threadIdx.x] = 0.0;
}

__global__ __launch_bounds__(NTHREADS, 2)
void vacf_main_kernel(const float* __restrict__ vel, int W) {
    extern __shared__ float sh[];   // [SH_ROWS][CB]

    const int tid  = threadIdx.x;
    const int warp = tid >> 5;
    const int lane = tid & 31;
    const int j0   = blockIdx.x * CB;   // column tile base
    const int i0   = blockIdx.y * TT;   // time tile base

    // ---- Load tile (zero-padded outside [0,T) x [0,D)) ----
    #pragma unroll 4
    for (int idx = tid; idx < SH_ROWS * CB; idx += NTHREADS) {
        int row = idx >> 6;      // / CB
        int col = idx & (CB - 1);
        int gi = i0 + row;
        int gj = j0 + col;
        float v = 0.0f;
        if (gi < T_DIM && gj < D_DIM) v = vel[gi * D_DIM + gj];
        sh[row * CB + col] = v;
    }
    __syncthreads();

    // ---- Compute: warp handles lags [t0, t0+12]; lane handles column pair (2*lane, 2*lane+1) ----
    const int t0 = warp * LPW;
    const unsigned long long* sh2 = (const unsigned long long*)sh; // row stride = 32 ull

    unsigned long long w[LPW];     // sliding window: w[(k+r)%13] = x[k + t0 + r]
    unsigned long long acc[LPW];
    #pragma unroll
    for (int r = 0; r < LPW; r++) {
        w[r]   = sh2[(t0 + r) * 32 + lane];
        acc[r] = 0ULL;
    }

    const unsigned long long* pb = sh2 + lane;                 // base stream x[i]
    const unsigned long long* pw = sh2 + lane + (t0 + LPW) * 32; // window refill x[i + t0 + 13]

    for (int i = 0; i < TT; i += LPW) {
        #pragma unroll
        for (int k = 0; k < LPW; k++) {
            unsigned long long b = pb[k * 32];
            #pragma unroll
            for (int r = 0; r < LPW; r++) {
                acc[r] = ffma2(b, w[(k + r) % LPW], acc[r]);
            }
            w[k] = pw[k * 32];   // x[i + k + t0 + 13], overwrites slot just vacated
        }
        pb += LPW * 32;
        pw += LPW * 32;
    }

    // ---- Reduce over lanes (columns) and accumulate into global band sums ----
    #pragma unroll
    for (int r = 0; r < LPW; r++) {
        float lo = __uint_as_float((unsigned int)(acc[r] & 0xffffffffULL));
        float hi = __uint_as_float((unsigned int)(acc[r] >> 32));
        float v = lo + hi;
        #pragma unroll
        for (int off = 16; off > 0; off >>= 1)
            v += __shfl_xor_sync(0xffffffffu, v, off);
        int t = t0 + r;
        if (lane == 0 && t < W) atomicAdd(&g_sum[t], (double)v);
    }
}

__global__ void vacf_fin_kernel(float* __restrict__ out, int W) {
    int t = blockIdx.x * blockDim.x + threadIdx.x;
    if (t < W) {
        double denom = (double)(T_DIM - t) * (double)D_DIM;
        out[t] = (float)(g_sum[t] / denom);
    }
}

extern "C" void kernel_launch(void* const* d_in, const int* in_sizes, int n_in,
                              void* d_out, int out_size) {
    const float* vel = (const float*)d_in[0];
    int W = out_size;   // 100

    size_t shbytes = (size_t)SH_ROWS * CB * sizeof(float);  // 79,872 B
    cudaFuncSetAttribute(vacf_main_kernel,
                         cudaFuncAttributeMaxDynamicSharedMemorySize, (int)shbytes);

    vacf_zero_kernel<<<1, 128>>>();

    dim3 grid((D_DIM + CB - 1) / CB,        // 47
              (T_DIM + TT - 1) / TT);       // 49
    vacf_main_kernel<<<grid, NTHREADS, shbytes>>>(vel, W);

    vacf_fin_kernel<<<1, 128>>>((float*)d_out, W);
}